// round 12
// baseline (speedup 1.0000x reference)
#include <cuda_runtime.h>
#include <cuda_bf16.h>
#include <math.h>

// SimDiff: right[f,i] = cos(x[f,i], x[f+iv, i+1])      (i < tpf-1)
//          down [f,i] = cos(x[f,i], x[f+iv, i+width])  (i < tpf-width)
// else -1. Output: [right | down], each frames*tpf f32.
//
// R10 (warp co-scheduling, 2.25x ideal) = 37.4us with ~50% of the ideal
// merge realized. This round improves the SHARING RATIO, not the pacing:
// PAIRED-DIAGONAL TILES (iv==1 path). down-target of (f,i) = (f+1,i+width)
// lies on diagonal d+(width-1). A CTA pairs chains dA and dB=dA+width-1 over
// the same 4-frame window:
//   warps 0-3: chain A, frames F..F+3;  warps 4-7: chain B, same frames.
//   A right-shares (3) + B right-shares (3) + A-down==B-anchor (3) +
//   A-down(F+3)==B-right(F+3) (1)  -> distinct = 14 / 24 uses = 0.583x.
// Exact cover: d-axis split into A/B halves of 2(width-1)-blocks, frames in
// 4-blocks. Body = unchanged 40-reg R2 stream loop, no barriers.
// iv!=1 (or width<2) falls back to the proven R10 lattice decode.

#define EPSN 1e-8f

template <int NPL>
__device__ __forceinline__ void sim_body(
    const float* __restrict__ x,
    float* __restrict__ outR, float* __restrict__ outD,
    int t, int tb, int tc, bool wr, bool vr, bool vd, int lane)
{
    const int D = NPL * 128;
    const float4* __restrict__ a4 =
        reinterpret_cast<const float4*>(x + (size_t)t * D) + lane;
    const float4* __restrict__ b4 =
        reinterpret_cast<const float4*>(x + (size_t)tb * D) + lane;
    const float4* __restrict__ c4 =
        reinterpret_cast<const float4*>(x + (size_t)tc * D) + lane;

    float na = 0.0f, d1 = 0.0f, n1 = 0.0f, d2 = 0.0f, n2 = 0.0f;

    float4 a = a4[0];
    float4 b = b4[0];
    float4 c = c4[0];
#pragma unroll
    for (int k = 0; k < NPL; k++) {
        float4 ac = a, bc = b, cc = c;
        if (k + 1 < NPL) {
            a = a4[32 * (k + 1)];
            b = b4[32 * (k + 1)];
            c = c4[32 * (k + 1)];
        }
        na = fmaf(ac.x, ac.x, na); na = fmaf(ac.y, ac.y, na);
        na = fmaf(ac.z, ac.z, na); na = fmaf(ac.w, ac.w, na);
        d1 = fmaf(ac.x, bc.x, d1); d1 = fmaf(ac.y, bc.y, d1);
        d1 = fmaf(ac.z, bc.z, d1); d1 = fmaf(ac.w, bc.w, d1);
        n1 = fmaf(bc.x, bc.x, n1); n1 = fmaf(bc.y, bc.y, n1);
        n1 = fmaf(bc.z, bc.z, n1); n1 = fmaf(bc.w, bc.w, n1);
        d2 = fmaf(ac.x, cc.x, d2); d2 = fmaf(ac.y, cc.y, d2);
        d2 = fmaf(ac.z, cc.z, d2); d2 = fmaf(ac.w, cc.w, d2);
        n2 = fmaf(cc.x, cc.x, n2); n2 = fmaf(cc.y, cc.y, n2);
        n2 = fmaf(cc.z, cc.z, n2); n2 = fmaf(cc.w, cc.w, n2);
    }

#pragma unroll
    for (int off = 16; off > 0; off >>= 1) {
        na += __shfl_xor_sync(0xFFFFFFFFu, na, off);
        d1 += __shfl_xor_sync(0xFFFFFFFFu, d1, off);
        n1 += __shfl_xor_sync(0xFFFFFFFFu, n1, off);
        d2 += __shfl_xor_sync(0xFFFFFFFFu, d2, off);
        n2 += __shfl_xor_sync(0xFFFFFFFFu, n2, off);
    }

    if (lane == 0 && wr) {
        const float nA = fmaxf(sqrtf(na), EPSN);
        outR[t] = vr ? d1 / (nA * fmaxf(sqrtf(n1), EPSN)) : -1.0f;
        outD[t] = vd ? d2 / (nA * fmaxf(sqrtf(n2), EPSN)) : -1.0f;
    }
}

template <int NPL>  // D = NPL * 128 floats
__global__ void __launch_bounds__(256, 6) simdiff_pair_kernel(
    const float* __restrict__ x,
    const int* __restrict__ p_frames,
    const int* __restrict__ p_height,
    const int* __restrict__ p_width,
    const int* __restrict__ p_interval,
    float* __restrict__ out,
    int total)
{
    const int width  = *p_width;
    const int height = *p_height;
    const int frames = *p_frames;
    const int iv     = *p_interval;
    const int tpf    = width * height;

    const int wib  = threadIdx.x >> 5;      // 0..7
    const int lane = threadIdx.x & 31;

    float* __restrict__ outR = out;
    float* __restrict__ outD = out + total;

    if (iv == 1 && width >= 2) {
        // ---- paired-diagonal tiling ----
        const int W1 = width - 1;
        const int ndelta = frames + tpf - 1;          // delta' = i - f + frames-1
        const int npq = (ndelta + 2 * W1 - 1) / (2 * W1);
        const int nF  = (frames + 3) >> 2;
        const long ntile = (long)npq * W1 * nF;

        const int dtok = tpf + 1;
        const int ctok = tpf + width;

        for (long p = blockIdx.x; p < ntile; p += gridDim.x) {
            const long t1 = p / W1;
            const int  r  = (int)(p - t1 * W1);
            const int  s  = (int)(t1 / npq);
            const int  q  = (int)(t1 - (long)s * npq);

            // diagonal for this warp: A half (w<4) or B half (w>=4)
            const int dpA = q * 2 * W1 + r;                 // delta' of chain A
            const int dp  = (wib < 4) ? dpA : dpA + W1;     // this warp's delta'
            const int f   = 4 * s + (wib & 3);
            const int i   = f + dp - (frames - 1);

            const bool valid = (f < frames) && (i >= 0) && (i < tpf);
            const int  t  = valid ? f * tpf + i : 0;
            const bool vf = valid && (f + 1 < frames);
            const bool vr = vf && (i + 1 < tpf);
            const bool vd = vf && (i < tpf - width);
            const int  tb = vr ? t + dtok : t;
            const int  tc = vd ? t + ctok : t;

            sim_body<NPL>(x, outR, outD, t, tb, tc, valid, vr, vd, lane);
        }
    } else {
        // ---- general-iv fallback: R10 lattice (CW=2 x CL=4), proven ----
        const int nch_a = iv * tpf;
        const int nch_b = frames > iv ? frames - iv : 0;
        const int nch   = nch_a + nch_b;
        const int maxL  = min((frames + iv - 1) / iv, tpf);
        const int ncb = (nch + 1) >> 1;
        const int nsb = (maxL + 3) >> 2;
        const long ntile = (long)ncb * nsb;

        const int jj = wib & 1;
        const int kk = wib >> 1;
        const int dtok = iv * tpf + 1;
        const int ctok = iv * tpf + width;

        for (long p = blockIdx.x; p < ntile; p += gridDim.x) {
            const int cb = (int)(p % ncb);
            const int sb = (int)(p / ncb);

            const int ci = cb * 2 + jj;
            if (ci >= nch) continue;

            int f0, i0;
            if (ci < nch_a) { f0 = ci % iv; i0 = ci / iv; }
            else            { f0 = iv + (ci - nch_a); i0 = 0; }
            if (f0 >= frames || i0 >= tpf) continue;

            const int Lc = min((frames - f0 + iv - 1) / iv, tpf - i0);
            const int s  = sb * 4 + kk;
            if (s >= Lc) continue;

            const int fA = f0 + s * iv;
            const int iA = i0 + s;
            const int t  = fA * tpf + iA;

            const bool vf = (fA + iv) < frames;
            if (!vf) {
                if (lane == 0) { outR[t] = -1.0f; outD[t] = -1.0f; }
                continue;
            }
            const bool vr = (iA + 1 < tpf);
            const bool vd = (iA < tpf - width);
            const int tb = vr ? t + dtok : t;
            const int tc = vd ? t + ctok : t;

            sim_body<NPL>(x, outR, outD, t, tb, tc, true, vr, vd, lane);
        }
    }
}

// Generic fallback for arbitrary D (scalar loads, one warp per token).
__global__ void __launch_bounds__(256) simdiff_generic_kernel(
    const float* __restrict__ x,
    const int* __restrict__ p_frames,
    const int* __restrict__ p_height,
    const int* __restrict__ p_width,
    const int* __restrict__ p_interval,
    float* __restrict__ out,
    int total, int D)
{
    const int gwarp = (blockIdx.x * blockDim.x + threadIdx.x) >> 5;
    const int lane  = threadIdx.x & 31;
    if (gwarp >= total) return;

    const int width    = *p_width;
    const int height   = *p_height;
    const int frames   = *p_frames;
    const int interval = *p_interval;
    const int tpf      = width * height;

    const int f = gwarp / tpf;
    const int i = gwarp - f * tpf;

    float* __restrict__ outR = out;
    float* __restrict__ outD = out + total;

    const bool vf = (f + interval) < frames;
    if (!vf) {
        if (lane == 0) { outR[gwarp] = -1.0f; outD[gwarp] = -1.0f; }
        return;
    }
    const bool vr = (i < tpf - 1);
    const bool vd = (i < tpf - width);

    const size_t bframe = (size_t)(f + interval) * tpf + i;
    const size_t i1 = vr ? (bframe + 1)     : bframe;
    const size_t i2 = vd ? (bframe + width) : bframe;

    const float* a = x + (size_t)gwarp * D;
    const float* b = x + i1 * D;
    const float* c = x + i2 * D;

    float na = 0.0f, d1 = 0.0f, n1 = 0.0f, d2 = 0.0f, n2 = 0.0f;
    for (int k = lane; k < D; k += 32) {
        float av = a[k], bv = b[k], cv = c[k];
        na = fmaf(av, av, na);
        d1 = fmaf(av, bv, d1); n1 = fmaf(bv, bv, n1);
        d2 = fmaf(av, cv, d2); n2 = fmaf(cv, cv, n2);
    }

#pragma unroll
    for (int off = 16; off > 0; off >>= 1) {
        na += __shfl_xor_sync(0xFFFFFFFFu, na, off);
        d1 += __shfl_xor_sync(0xFFFFFFFFu, d1, off);
        n1 += __shfl_xor_sync(0xFFFFFFFFu, n1, off);
        d2 += __shfl_xor_sync(0xFFFFFFFFu, d2, off);
        n2 += __shfl_xor_sync(0xFFFFFFFFu, n2, off);
    }

    if (lane == 0) {
        const float nA = fmaxf(sqrtf(na), EPSN);
        outR[gwarp] = vr ? d1 / (nA * fmaxf(sqrtf(n1), EPSN)) : -1.0f;
        outD[gwarp] = vd ? d2 / (nA * fmaxf(sqrtf(n2), EPSN)) : -1.0f;
    }
}

extern "C" void kernel_launch(void* const* d_in, const int* in_sizes, int n_in,
                              void* d_out, int out_size) {
    const float* x        = (const float*)d_in[0];
    const int* p_frames   = (const int*)d_in[1];
    const int* p_height   = (const int*)d_in[2];
    const int* p_width    = (const int*)d_in[3];
    const int* p_interval = (const int*)d_in[4];
    float* out = (float*)d_out;

    const int total = out_size / 2;            // frames * tpf
    const int D     = in_sizes[0] / total;     // hidden dim

    if (D == 1152 || D == 1024 || D == 1280) {
        // ~total/8 useful tiles + diagonal-edge padding; grid-stride covers
        // any shape, surplus tiles exit at the loop bound immediately.
        const int blocks = total / 8 + 1536;
        if (D == 1152) {
            simdiff_pair_kernel<9><<<blocks, 256>>>(
                x, p_frames, p_height, p_width, p_interval, out, total);
        } else if (D == 1024) {
            simdiff_pair_kernel<8><<<blocks, 256>>>(
                x, p_frames, p_height, p_width, p_interval, out, total);
        } else {
            simdiff_pair_kernel<10><<<blocks, 256>>>(
                x, p_frames, p_height, p_width, p_interval, out, total);
        }
    } else {
        const int blocks = (total + 7) / 8;
        simdiff_generic_kernel<<<blocks, 256>>>(
            x, p_frames, p_height, p_width, p_interval, out, total, D);
    }
}